// round 6
// baseline (speedup 1.0000x reference)
#include <cuda_runtime.h>

#define T_STEPS 1024
#define BATCH   2048
#define N1      30
#define N2      60

using ull = unsigned long long;

// ---- transposed, lane-major weight tables (filled by setup kernel each launch) ----
// [k][lane][4] : lane-major so a warp's LDG.128 of chunk k is 512B coalesced.
__device__ __align__(16) float g_W11t [8][32][4];  // W11[lane][4k+j]      (pad 0)
__device__ __align__(16) float g_W21ta[8][32][4];  // (W21*M)[2*lane][4k+j]
__device__ __align__(16) float g_W21tb[8][32][4];  // (W21*M)[2*lane+1][4k+j]

__global__ void setup_weights(const float* __restrict__ W11,
                              const float* __restrict__ W21,
                              const float* __restrict__ M21)
{
    int idx  = threadIdx.x;          // 0..1023
    int k    = idx >> 7;
    int lane = (idx >> 2) & 31;
    int j    = idx & 3;
    int col  = 4 * k + j;
    bool okc = (lane < N1) && (col < N1);
    g_W11t[k][lane][j] = okc ? W11[lane * N1 + col] : 0.f;
    int ra = 2 * lane, rb = 2 * lane + 1;
    g_W21ta[k][lane][j] = okc ? W21[ra * N1 + col] * M21[ra * N1 + col] : 0.f;
    g_W21tb[k][lane][j] = okc ? W21[rb * N1 + col] * M21[rb * N1 + col] : 0.f;
}

// packed fp32x2 FMA
__device__ __forceinline__ ull ffma2(ull a, ull b, ull c) {
    ull d;
    asm("fma.rn.f32x2 %0, %1, %2, %3;" : "=l"(d) : "l"(a), "l"(b), "l"(c));
    return d;
}
__device__ __forceinline__ ull pk2(float x, float y) {
    ull r;
    asm("mov.b64 %0, {%1, %2};" : "=l"(r) : "f"(x), "f"(y));
    return r;
}
__device__ __forceinline__ float hadd2(ull v) {
    float a, b;
    asm("mov.b64 {%0, %1}, %2;" : "=f"(a), "=f"(b) : "l"(v));
    return a + b;
}
// fast tanh, ~1e-6 rel err; pre-activations bounded, no clamp needed
__device__ __forceinline__ float ftanh(float x) {
    float e = __expf(-2.f * x);
    return __fdividef(1.f - e, 1.f + e);
}

// Block = 64 threads = 2 warps; each warp autonomously owns ONE batch element.
__global__ void __launch_bounds__(64, 7) hier_rnn_kernel(
    const float* __restrict__ inp,    // (T, B, 1)
    const float* __restrict__ noise1, // (T, B, N1)
    const float* __restrict__ noise2, // (T, B, N2)
    const float* __restrict__ W22,    // (N2, N2)
    const float* __restrict__ Win,    // (N1,)
    const float* __restrict__ Wout,   // (N2,)
    float* __restrict__ out)          // (T, B, 1)
{
    __shared__ __align__(16) float s1buf[2][32];   // r1 per warp (pads 30..31 stay 0)
    __shared__ __align__(16) float s2buf[2][64];   // r2 per warp (pads 60..63 stay 0)

    const int tid  = threadIdx.x;
    const int warp = tid >> 5;
    const int l    = tid & 31;
    const int b    = blockIdx.x * 2 + warp;

    float* s1e = s1buf[warp];
    float* s2e = s2buf[warp];

    const bool act = (l < N1);
    const int  ls  = act ? l : 0;
    const int  ra  = 2 * ls;
    const int  rb  = 2 * ls + 1;

    // ---- W22 rows (2 per lane) in registers, f32x2-packed: 120 regs ----
    // w22a[2k], w22a[2k+1] pair with v2[k].x/.y — full 60-element row (R2-proven layout)
    ull w22a[30], w22b[30];
    #pragma unroll
    for (int k = 0; k < 30; k++) {
        float2 w = act ? *(const float2*)(W22 + ra * N2 + 2 * k) : make_float2(0.f, 0.f);
        w22a[k] = pk2(w.x, w.y);
        w = act ? *(const float2*)(W22 + rb * N2 + 2 * k) : make_float2(0.f, 0.f);
        w22b[k] = pk2(w.x, w.y);
    }
    const float winl  = act ? Win[l]   : 0.f;
    const float wouta = act ? Wout[ra] : 0.f;
    const float woutb = act ? Wout[rb] : 0.f;

    // ---- zero state (incl. pads, which are never overwritten) ----
    ((float*)s1buf)[tid] = 0.f;
    ((float*)s2buf)[tid] = 0.f;
    ((float*)s2buf)[tid + 64] = 0.f;
    __syncthreads();

    // ---- streaming pointers (inactive lanes alias row 0 — loads harmless) ----
    const float* pn1 = noise1 + (long long)b * N1 + ls;
    const float* pn2 = noise2 + (long long)b * N2 + ra;
    const float* px  = inp + b;
    float*       py  = out + b;

    const ulonglong2* v2 = (const ulonglong2*)s2e;   // 15 x 16B = full 60 floats
    const ulonglong2* v1 = (const ulonglong2*)s1e;   // 8 x 16B (30 + 2 pad)

    for (int t = 0; t < T_STEPS; t++) {
        // current-step inputs, issued at loop top (long load->use distance)
        float  xv  = __ldg(px);
        float  n1v = __ldg(pn1);
        float2 n2v = *(const float2*)pn2;

        // ---- phase A: acc = W22[{ra,rb},:] . r2_old  (ALL 60 elements) ----
        ull acc_a = 0, acc_b = 0;
        #pragma unroll
        for (int k = 0; k < 15; k++) {
            ulonglong2 u = v2[k];
            acc_a = ffma2(w22a[2 * k],     u.x, acc_a);
            acc_a = ffma2(w22a[2 * k + 1], u.y, acc_a);
            acc_b = ffma2(w22b[2 * k],     u.x, acc_b);
            acc_b = ffma2(w22b[2 * k + 1], u.y, acc_b);
        }

        // ---- phase B: r1 update; W11 streamed from L1-resident table ----
        ull a1 = 0;
        #pragma unroll
        for (int k = 0; k < 8; k++) {
            float4 w = *(const float4*)g_W11t[k][l];   // coalesced LDG.128, L1 hit
            ulonglong2 u = v1[k];                      // broadcast LDS of r1_old
            a1 = ffma2(pk2(w.x, w.y), u.x, a1);
            a1 = ffma2(pk2(w.z, w.w), u.y, a1);
        }
        float r1n = ftanh(fmaf(winl, xv, n1v) + hadd2(a1));

        __syncwarp();                     // all r1_old reads done
        if (act) s1e[l] = r1n;            // publish r1_new
        __syncwarp();

        // ---- phase C: acc += W21m[{ra,rb},:] . r1_new (streamed weights) ----
        #pragma unroll
        for (int k = 0; k < 8; k++) {
            float4 wa = *(const float4*)g_W21ta[k][l];
            float4 wb = *(const float4*)g_W21tb[k][l];
            ulonglong2 u = v1[k];                      // broadcast LDS of r1_new
            acc_a = ffma2(pk2(wa.x, wa.y), u.x, acc_a);
            acc_a = ffma2(pk2(wa.z, wa.w), u.y, acc_a);
            acc_b = ffma2(pk2(wb.x, wb.y), u.x, acc_b);
            acc_b = ffma2(pk2(wb.z, wb.w), u.y, acc_b);
        }

        // ---- phase D: tanh, publish r2, then y reduction off the critical path ----
        float r2a = ftanh(n2v.x + hadd2(acc_a));
        float r2b = ftanh(n2v.y + hadd2(acc_b));
        if (act) *(float2*)(s2e + ra) = make_float2(r2a, r2b);

        float yp = wouta * r2a + woutb * r2b;          // 0 on inactive lanes
        #pragma unroll
        for (int o = 16; o > 0; o >>= 1)
            yp += __shfl_xor_sync(0xffffffffu, yp, o);
        if (l == 0) *py = yp;

        __syncwarp();                     // r2_new visible before next step's reads

        px  += BATCH;
        pn1 += BATCH * N1;
        pn2 += BATCH * N2;
        py  += BATCH;
    }
}

extern "C" void kernel_launch(void* const* d_in, const int* in_sizes, int n_in,
                              void* d_out, int out_size)
{
    const float *inp = nullptr, *n1 = nullptr, *n2 = nullptr;
    const float *W11 = nullptr, *W22 = nullptr, *W21 = nullptr, *M21 = nullptr;
    const float *Win = nullptr, *Wout = nullptr;

    for (int i = 0; i < n_in; i++) {
        const float* p = (const float*)d_in[i];
        switch (in_sizes[i]) {
            case T_STEPS * BATCH:          inp = p; break;
            case T_STEPS * BATCH * N1:     n1  = p; break;
            case T_STEPS * BATCH * N2:     n2  = p; break;
            case N1 * N1:                  W11 = p; break;
            case N2 * N2:                  W22 = p; break;
            case N2 * N1:                                   // appears twice (W21, mask)
                if (!W21) W21 = p; else M21 = p;            // product commutes
                break;
            case N1:                       Win = p; break;
            case N2:                       Wout = p; break;
        }
    }

    setup_weights<<<1, 1024>>>(W11, W21, M21);
    // 1024 blocks x 2 warps x 1 batch element = 2048; 7 blocks/SM -> single wave
    hier_rnn_kernel<<<BATCH / 2, 64>>>(inp, n1, n2, W22, Win, Wout, (float*)d_out);
}

// round 7
// speedup vs baseline: 1.4519x; 1.4519x over previous
#include <cuda_runtime.h>

#define T_STEPS 1024
#define BATCH   2048
#define N1      30
#define N2      60

using ull = unsigned long long;

// ---- transposed, slot-major weight tables (L1-resident; filled each launch) ----
// g_W11t[k][slot][4]: W11[slot][4k+j], slot=row (0..29), slots 30..31 zero.
// g_W21t[k][slot][4]: (W21*M)[slot][4k+j], slot=row (0..59), slots 60..63 zero.
__device__ __align__(16) float g_W11t[8][32][4];
__device__ __align__(16) float g_W21t[8][64][4];

__global__ void setup_weights(const float* __restrict__ W11,
                              const float* __restrict__ W21,
                              const float* __restrict__ M21)
{
    int i = blockIdx.x * blockDim.x + threadIdx.x;   // 0..2047
    if (i < 1024) {                                   // W11 table: 8*32*4
        int k = i >> 7, slot = (i >> 2) & 31, j = i & 3;
        int col = 4 * k + j;
        bool ok = (slot < N1) && (col < N1);
        g_W11t[k][slot][j] = ok ? W11[slot * N1 + col] : 0.f;
    }
    if (i < 2048) {                                   // W21m table: 8*64*4
        int k = i >> 8, slot = (i >> 2) & 63, j = i & 3;
        int col = 4 * k + j;
        bool ok = (slot < N2) && (col < N1);
        g_W21t[k][slot][j] = ok ? W21[slot * N1 + col] * M21[slot * N1 + col] : 0.f;
    }
}

// packed fp32x2 FMA
__device__ __forceinline__ ull ffma2(ull a, ull b, ull c) {
    ull d;
    asm("fma.rn.f32x2 %0, %1, %2, %3;" : "=l"(d) : "l"(a), "l"(b), "l"(c));
    return d;
}
__device__ __forceinline__ ull pk2(float x, float y) {
    ull r;
    asm("mov.b64 %0, {%1, %2};" : "=l"(r) : "f"(x), "f"(y));
    return r;
}
__device__ __forceinline__ float hadd2(ull v) {
    float a, b;
    asm("mov.b64 {%0, %1}, %2;" : "=f"(a), "=f"(b) : "l"(v));
    return a + b;
}
__device__ __forceinline__ float ftanh(float x) {
    float e = __expf(-2.f * x);
    return __fdividef(1.f - e, 1.f + e);
}

// Block = 64 threads = 2 warps, owning batch pair (b0, b0+1).
// r2 rows: warp w, lane l<30 owns row w*30+l  (W22 row in regs: 30 ull = 60 regs)
// r1 rows: warp w, lane l<15 owns row w*15+l  (W11 streamed from table)
__global__ void __launch_bounds__(64, 7) hier_rnn_kernel(
    const float* __restrict__ inp,    // (T, B, 1)
    const float* __restrict__ noise1, // (T, B, N1)
    const float* __restrict__ noise2, // (T, B, N2)
    const float* __restrict__ W22,    // (N2, N2)
    const float* __restrict__ Win,    // (N1,)
    const float* __restrict__ Wout,   // (N2,)
    float* __restrict__ out)          // (T, B, 1)
{
    __shared__ __align__(16) float s1buf[2][2][32];  // [buf][elem][slot] pads 30,31 = 0
    __shared__ __align__(16) float s2buf[2][2][64];  // [buf][elem][row]  (60 used = 15x16B exact)
    __shared__ float2 ypart[2];                      // per-warp y partials (elem0, elem1)

    const int tid  = threadIdx.x;
    const int w    = tid >> 5;
    const int l    = tid & 31;
    const int b0   = blockIdx.x * 2;

    const bool actA = (l < 30);                 // owns an r2 row
    const bool actB = (l < 15);                 // owns an r1 row
    const int  row2 = w * 30 + (actA ? l : 29); // clamped for memory addressing
    const int  slot2 = actA ? (w * 30 + l) : 60;  // table slot (60+ = zeros)
    const int  row1 = w * 15 + (actB ? l : 0);
    const int  slot1 = actB ? (w * 15 + l) : 30;  // table slot (30+ = zeros)

    // ---- W22 row in registers: 30 ull = 60 regs ----
    ull w22[30];
    #pragma unroll
    for (int k = 0; k < 30; k++) {
        float2 v = actA ? *(const float2*)(W22 + row2 * N2 + 2 * k) : make_float2(0.f, 0.f);
        w22[k] = pk2(v.x, v.y);
    }
    const float winl  = actB ? Win[row1]  : 0.f;
    const float woutl = actA ? Wout[row2] : 0.f;

    // ---- zero state (both buffers, incl. r1 pads) ----
    ((float*)s1buf)[tid]       = 0.f;  ((float*)s1buf)[tid + 64]  = 0.f;
    ((float*)s2buf)[tid]       = 0.f;  ((float*)s2buf)[tid + 64]  = 0.f;
    ((float*)s2buf)[tid + 128] = 0.f;  ((float*)s2buf)[tid + 192] = 0.f;
    __syncthreads();

    // ---- streaming pointers ----
    const float* pn1 = noise1 + (long long)b0 * N1 + row1;
    const float* pn2 = noise2 + (long long)b0 * N2 + row2;
    const float* px  = inp + b0;
    float*       py  = out + b0;

    for (int t = 0; t < T_STEPS; t++) {
        const int cur = t & 1, nxt = cur ^ 1;

        // current-step inputs (long load->use distance)
        float2 xv  = *(const float2*)px;                 // both elems, broadcast
        float n1v0 = __ldg(pn1), n1v1 = __ldg(pn1 + N1);
        float n2v0 = __ldg(pn2), n2v1 = __ldg(pn2 + N2);

        const ulonglong2* v2e0 = (const ulonglong2*)s2buf[cur][0];
        const ulonglong2* v2e1 = (const ulonglong2*)s2buf[cur][1];
        const ulonglong2* v1e0 = (const ulonglong2*)s1buf[cur][0];
        const ulonglong2* v1e1 = (const ulonglong2*)s1buf[cur][1];

        // ---- phase A: acc_e = W22[row2,:] . r2_old[e]  (2 independent chains) ----
        ull acc0 = 0, acc1 = 0;
        #pragma unroll
        for (int k = 0; k < 15; k++) {
            ulonglong2 u0 = v2e0[k];
            ulonglong2 u1 = v2e1[k];
            acc0 = ffma2(w22[2 * k],     u0.x, acc0);
            acc0 = ffma2(w22[2 * k + 1], u0.y, acc0);
            acc1 = ffma2(w22[2 * k],     u1.x, acc1);
            acc1 = ffma2(w22[2 * k + 1], u1.y, acc1);
        }

        // ---- phase B: r1 row update (15 lanes per warp), W11 streamed ----
        ull a10 = 0, a11 = 0;
        #pragma unroll
        for (int k = 0; k < 8; k++) {
            float4 wv = *(const float4*)g_W11t[k][slot1];  // L1-hit LDG.128
            ull wx = pk2(wv.x, wv.y), wy = pk2(wv.z, wv.w);
            ulonglong2 u0 = v1e0[k];
            ulonglong2 u1 = v1e1[k];
            a10 = ffma2(wx, u0.x, a10);
            a10 = ffma2(wy, u0.y, a10);
            a11 = ffma2(wx, u1.x, a11);
            a11 = ffma2(wy, u1.y, a11);
        }
        float r1n0 = ftanh(fmaf(winl, xv.x, n1v0) + hadd2(a10));
        float r1n1 = ftanh(fmaf(winl, xv.y, n1v1) + hadd2(a11));
        if (actB) {
            s1buf[nxt][0][row1] = r1n0;       // publish to NEXT buffer (no read conflict)
            s1buf[nxt][1][row1] = r1n1;
        }
        __syncthreads();                       // bar1: r1_new visible

        // ---- phase C: acc_e += W21m[row2,:] . r1_new[e]  (streamed weights) ----
        const ulonglong2* v1n0 = (const ulonglong2*)s1buf[nxt][0];
        const ulonglong2* v1n1 = (const ulonglong2*)s1buf[nxt][1];
        #pragma unroll
        for (int k = 0; k < 8; k++) {
            float4 wv = *(const float4*)g_W21t[k][slot2];
            ull wx = pk2(wv.x, wv.y), wy = pk2(wv.z, wv.w);
            ulonglong2 u0 = v1n0[k];
            ulonglong2 u1 = v1n1[k];
            acc0 = ffma2(wx, u0.x, acc0);
            acc0 = ffma2(wy, u0.y, acc0);
            acc1 = ffma2(wx, u1.x, acc1);
            acc1 = ffma2(wy, u1.y, acc1);
        }

        float r2n0 = ftanh(n2v0 + hadd2(acc0));
        float r2n1 = ftanh(n2v1 + hadd2(acc1));
        if (actA) {
            s2buf[nxt][0][row2] = r2n0;
            s2buf[nxt][1][row2] = r2n1;
        }

        // ---- y partials: per-warp butterfly over this warp's 30 rows ----
        float yp0 = woutl * r2n0;              // 0 on inactive lanes
        float yp1 = woutl * r2n1;
        #pragma unroll
        for (int o = 16; o > 0; o >>= 1) {
            yp0 += __shfl_xor_sync(0xffffffffu, yp0, o);
            yp1 += __shfl_xor_sync(0xffffffffu, yp1, o);
        }
        if (l == 0) ypart[w] = make_float2(yp0, yp1);

        __syncthreads();                       // bar2: r2_new + ypart visible

        if (tid == 0) {                        // y finalize, overlaps next step's A
            float2 pa = ypart[0], pb = ypart[1];
            *(float2*)py = make_float2(pa.x + pb.x, pa.y + pb.y);
        }

        px  += BATCH;
        pn1 += BATCH * N1;
        pn2 += BATCH * N2;
        py  += BATCH;
    }
}

extern "C" void kernel_launch(void* const* d_in, const int* in_sizes, int n_in,
                              void* d_out, int out_size)
{
    const float *inp = nullptr, *n1 = nullptr, *n2 = nullptr;
    const float *W11 = nullptr, *W22 = nullptr, *W21 = nullptr, *M21 = nullptr;
    const float *Win = nullptr, *Wout = nullptr;

    for (int i = 0; i < n_in; i++) {
        const float* p = (const float*)d_in[i];
        switch (in_sizes[i]) {
            case T_STEPS * BATCH:          inp = p; break;
            case T_STEPS * BATCH * N1:     n1  = p; break;
            case T_STEPS * BATCH * N2:     n2  = p; break;
            case N1 * N1:                  W11 = p; break;
            case N2 * N2:                  W22 = p; break;
            case N2 * N1:                                   // appears twice (W21, mask)
                if (!W21) W21 = p; else M21 = p;            // product commutes
                break;
            case N1:                       Win = p; break;
            case N2:                       Wout = p; break;
        }
    }

    setup_weights<<<2, 1024>>>(W11, W21, M21);
    // 1024 blocks x 2 warps, 2 batch elems per block; 7 blocks/SM -> single wave
    hier_rnn_kernel<<<BATCH / 2, 64>>>(inp, n1, n2, W22, Win, Wout, (float*)d_out);
}